// round 9
// baseline (speedup 1.0000x reference)
#include <cuda_runtime.h>
#include <math.h>

#define NBLK 148
#define NT   512
#define BN   8000
#define TT   128
typedef unsigned long long ull;

// ---------- static device scratch ----------
__device__ float g_xT[TT * BN];
__device__ float g_mT[TT * BN];
__device__ float g_M4[2000 * 500];   // Af, Af^2, Ab, Ab^2
__device__ float g_M2[1000 * 500];   // Af, Ab
__device__ float g_h[64 * BN];
__device__ float g_xin[64 * BN];
__device__ float g_Ddec[128 * BN];
__device__ float g_rh[64 * BN];
__device__ float g_u[64 * BN];
__device__ float g_Dgd[264 * BN];
__device__ float g_Dcd[264 * BN];
__device__ float g_x1[BN];
__device__ float g_x2[BN];
__device__ float g_Wru[128 * 330];
__device__ float g_Wp[64 * 192];
__device__ float g_bru[128];
__device__ float g_bp[64];
__device__ unsigned g_cnt;
__device__ volatile unsigned g_gen;

// ---------- f32x2 helpers ----------
__device__ __forceinline__ ull splat2(float x) {
    ull r; asm("mov.b64 %0,{%1,%1};" : "=l"(r) : "f"(x)); return r;
}
__device__ __forceinline__ void ffma2(ull& d, ull a, ull b) {
    asm("fma.rn.f32x2 %0,%1,%2,%3;" : "=l"(d) : "l"(a), "l"(b), "l"(d));
}
__device__ __forceinline__ float2 unpk(ull p) {
    float2 v; asm("mov.b64 {%0,%1},%2;" : "=f"(v.x), "=f"(v.y) : "l"(p)); return v;
}

// ---------- software grid barrier ----------
__device__ __forceinline__ void gsync() {
    __syncthreads();
    if (threadIdx.x == 0) {
        __threadfence();
        unsigned gen = g_gen;
        if (atomicAdd(&g_cnt, 1u) == NBLK - 1) {
            atomicExch(&g_cnt, 0u);
            __threadfence();
            g_gen = gen + 1;
        } else {
            while (g_gen == gen) __nanosleep(32);
        }
        __threadfence();
    }
    __syncthreads();
}

// ---------- conv input channel dispatch ----------
template <int KIND>
__device__ __forceinline__ const float* conv_in(int k, int t) {
    if (KIND == 0) {                       // [x1, mf, h]  K=66
        if (k == 0) return g_x1;
        if (k == 1) return g_mT + t * BN;
        return g_h + (k - 2) * BN;
    } else if (KIND == 1) {                // [Ddec(128), h]  K=192
        return (k < 128) ? g_Ddec + k * BN : g_h + (k - 128) * BN;
    } else if (KIND == 2) {                // [x2, mf, h, Dgd]  K=330
        if (k == 0) return g_x2;
        if (k == 1) return g_mT + t * BN;
        if (k < 66) return g_h + (k - 2) * BN;
        return g_Dgd + (k - 66) * BN;
    } else {                               // [x2, mf, rh, Dcd]  K=330
        if (k == 0) return g_x2;
        if (k == 1) return g_mT + t * BN;
        if (k < 66) return g_rh + (k - 2) * BN;
        return g_Dcd + (k - 66) * BN;
    }
}

// ---------- fused stage B (all 512 threads; out tile in sm_out) ----------
__device__ __forceinline__ void stageB_tile(int t, int n0, float* sm, const float* sm_out,
        const float* __restrict__ Wro, const float* __restrict__ bro,
        float* __restrict__ imp, float* __restrict__ reps) {
    const int tid = threadIdx.x;
    __syncthreads();
    if (tid < 128) sm[tid] = __ldg(Wro + tid);
    __syncthreads();
    const int q = tid >> 7, i = tid & 127;
    const int bn = n0 + i;
    float part = 0.f;
    if (bn < BN) {
        int b = bn / 500, n = bn - b * 500;
        int rbase = (b * 64000 + n) * 128 + t;
#pragma unroll 4
        for (int c = 16 * q; c < 16 * q + 16; c++) {
            float ov = sm_out[c * 128 + i];
            float hv = g_h[c * BN + bn];
            part += sm[c] * ov + sm[64 + c] * hv;
            reps[rbase + c * 64000] = ov;
            reps[rbase + (64 + c) * 64000] = hv;
        }
    }
    sm[128 + q * 128 + i] = part;
    __syncthreads();
    if (tid < 128) {
        int bn2 = n0 + tid;
        if (bn2 < BN) {
            float acc = __ldg(bro) + sm[128 + tid] + sm[256 + tid] + sm[384 + tid] + sm[512 + tid];
            imp[bn2 * TT + t] = acc;
            float m = g_mT[t * BN + bn2];
            g_x2[bn2] = (m > 0.5f) ? g_x1[bn2] : acc;
        }
    }
}

// ---------- fused stage A for t=tn (new-h tile in sm_out) ----------
__device__ __forceinline__ void stageA_tile(int tn, int n0, float* sm, const float* sm_out,
        const float* __restrict__ Wfs, const float* __restrict__ bfs,
        float* __restrict__ pred) {
    const int tid = threadIdx.x;
    __syncthreads();
    if (tid < 64) sm[tid] = __ldg(Wfs + tid);
    __syncthreads();
    const int q = tid >> 7, i = tid & 127;
    const int bn = n0 + i;
    float part = 0.f;
    if (bn < BN) {
#pragma unroll 4
        for (int c = 16 * q; c < 16 * q + 16; c++)
            part += sm[c] * sm_out[c * 128 + i];
    }
    sm[128 + q * 128 + i] = part;
    __syncthreads();
    if (tid < 128) {
        int bn2 = n0 + tid;
        if (bn2 < BN) {
            float acc = __ldg(bfs) + sm[128 + tid] + sm[256 + tid] + sm[384 + tid] + sm[512 + tid];
            pred[bn2 * TT + tn] = acc;
            float m = g_mT[tn * BN + bn2];
            g_x1[bn2] = (m > 0.5f) ? g_xT[tn * BN + bn2] : acc;
        }
    }
}

// ---------- conv GEMM (tile 64 O x 128 N, 512 threads), fused epilogues ----------
// EPI 0:->g_xin  1: prelu->sm_out + stageB  2: sigmoid->rh/u  3: tanh+GRU->h + stageA
template <int KIND, int EPI>
__device__ __forceinline__ void conv_stage(int t,
        const float* __restrict__ Wg, const float* __restrict__ bias,
        float* sm, float* sm_out,
        const float* Wro, const float* bro,
        const float* Wfs, const float* bfs, const float* pa,
        float* imp, float* pred, float* reps) {
    constexpr int K = (KIND == 0) ? 66 : (KIND == 1) ? 192 : 330;
    constexpr int NOROW = (KIND == 2) ? 2 : 1;
    float* Ws = sm;            // [8][68]
    float* Is = sm + 8 * 68;   // [8][132]
    const int tid = threadIdx.x;
    for (int tile = blockIdx.x; tile < NOROW * 63; tile += NBLK) {
        const int o0 = (tile / 63) * 64;
        const int n0 = (tile % 63) * 128;
        const int rg = (tid >> 5) * 4;       // 16 groups x 4 rows = 64
        const int cg = (tid & 31) * 4;       // 32 groups x 4 cols = 128
        ull acc[4][2];
#pragma unroll
        for (int i = 0; i < 4; i++) { acc[i][0] = 0ull; acc[i][1] = 0ull; }

        const int wrow = tid >> 3, wkk = tid & 7;        // Ws load map
        const int ikk = tid >> 6, ij = (tid & 63) * 2;   // Is load map (float2)
        float wv; float2 iv;
        {
            wv = (wkk < K) ? __ldg(Wg + (o0 + wrow) * K + wkk) : 0.f;
            int col = n0 + ij;
            iv = make_float2(0.f, 0.f);
            if (ikk < K && col < BN) iv = *(const float2*)(conv_in<KIND>(ikk, t) + col);
        }
        for (int k0 = 0; k0 < K; k0 += 8) {
            __syncthreads();
            Ws[wkk * 68 + wrow] = wv;
            *(float2*)&Is[ikk * 132 + ij] = iv;
            __syncthreads();
            if (k0 + 8 < K) {
                int kg = k0 + 8 + wkk;
                wv = (kg < K) ? __ldg(Wg + (o0 + wrow) * K + kg) : 0.f;
                int kgi = k0 + 8 + ikk, col = n0 + ij;
                iv = make_float2(0.f, 0.f);
                if (kgi < K && col < BN) iv = *(const float2*)(conv_in<KIND>(kgi, t) + col);
            }
#pragma unroll
            for (int kk = 0; kk < 8; kk++) {
                float4 a = *(const float4*)&Ws[kk * 68 + rg];
                ull av0 = splat2(a.x), av1 = splat2(a.y), av2 = splat2(a.z), av3 = splat2(a.w);
                ulonglong2 q0 = *(const ulonglong2*)&Is[kk * 132 + cg];
                ffma2(acc[0][0], av0, q0.x); ffma2(acc[0][1], av0, q0.y);
                ffma2(acc[1][0], av1, q0.x); ffma2(acc[1][1], av1, q0.y);
                ffma2(acc[2][0], av2, q0.x); ffma2(acc[2][1], av2, q0.y);
                ffma2(acc[3][0], av3, q0.x); ffma2(acc[3][1], av3, q0.y);
            }
        }
        float paval = (EPI == 1) ? __ldg(pa) : 0.f;
#pragma unroll
        for (int i = 0; i < 4; i++) {
            int o = o0 + rg + i;
            float bs = __ldg(bias + o);
#pragma unroll
            for (int j2 = 0; j2 < 2; j2++) {
                float2 v2 = unpk(acc[i][j2]);
#pragma unroll
                for (int e = 0; e < 2; e++) {
                    int bn = n0 + cg + 2 * j2 + e;
                    if (bn >= BN) continue;
                    float v = ((e == 0) ? v2.x : v2.y) + bs;
                    if (EPI == 0) {
                        g_xin[o * BN + bn] = v;
                    } else if (EPI == 1) {
                        sm_out[o * 128 + (bn - n0)] = (v >= 0.f) ? v : paval * v;
                    } else if (EPI == 2) {
                        float sv = 1.f / (1.f + expf(-v));
                        if (o < 64) g_rh[o * BN + bn] = sv * g_h[o * BN + bn];
                        else        g_u[(o - 64) * BN + bn] = sv;
                    } else {
                        float cv = tanhf(v);
                        int id = o * BN + bn;
                        float uu = g_u[id];
                        float hn = uu * g_h[id] + (1.f - uu) * cv;
                        g_h[id] = hn;
                        sm_out[o * 128 + (bn - n0)] = hn;
                    }
                }
            }
        }
        if (EPI == 1) stageB_tile(t, n0, sm, sm_out, Wro, bro, imp, reps);
        if (EPI == 3 && t + 1 < TT) stageA_tile(t + 1, n0, sm, sm_out, Wfs, bfs, pred);
    }
}

// ---------- diffusion GEMM: 128-row tiles, K=500, 512 threads ----------
// KIND 0: X=g_xin (M=1024), B=g_M2, N=1000, BC=64  -> g_Ddec   (128 tiles)
// KIND 1: X=[x2,mf,h] (M=1056), B=g_M4, N=2000, BC=128 -> g_Dgd (144 tiles)
// KIND 2: X=[x2,mf,rh] -> g_Dcd
template <int KIND>
__device__ __forceinline__ void diff_stage(int t, float* sm) {
    constexpr int M   = (KIND == 0) ? 1024 : 1056;
    constexpr int NC  = (KIND == 0) ? 1000 : 2000;
    constexpr int CCH = (KIND == 0) ? 64 : 66;
    constexpr int BC  = (KIND == 0) ? 64 : 128;
    constexpr int CPT = BC / 16;          // cols per thread: 4 or 8
    constexpr int UPT = CPT / 2;          // ull accs per row: 2 or 4
    constexpr int TM  = (M + 127) / 128;
    constexpr int TNC = (NC + BC - 1) / BC;
    const float* Bm = (KIND == 0) ? g_M2 : g_M4;
    float* Out = (KIND == 0) ? g_Ddec : ((KIND == 1) ? g_Dgd : g_Dcd);
    float* Xs = sm;            // [8][132]
    float* Bs = sm + 8 * 132;
    const int tid = threadIdx.x;
    for (int tile = blockIdx.x; tile < TM * TNC; tile += NBLK) {
        const int m0 = (tile / TNC) * 128;
        const int n0 = (tile % TNC) * BC;
        const int lr = tid >> 2, lk = (tid & 3) * 2;   // float2 loads
        const float* xrow = nullptr;
        {
            int gr = m0 + lr;
            if (gr < M) {
                if (KIND == 0) {
                    xrow = g_xin + gr * 500;
                } else {
                    int c = gr >> 4, b = gr & 15;
                    const float* base = (c == 0) ? g_x2
                                       : (c == 1) ? (g_mT + t * BN)
                                       : (((KIND == 1) ? g_h : g_rh) + (c - 2) * BN);
                    xrow = base + b * 500;
                }
            }
        }
        const float* brow = nullptr;
        if (lr < BC) { int gc = n0 + lr; if (gc < NC) brow = Bm + gc * 500; }
        const int rr = (tid >> 4) * 4;        // 32 groups x 4 rows = 128
        const int tc = (tid & 15) * CPT;      // 16 groups x CPT cols
        ull acc[4][UPT];
#pragma unroll
        for (int i = 0; i < 4; i++)
#pragma unroll
            for (int j = 0; j < UPT; j++) acc[i][j] = 0ull;

        float2 xv = make_float2(0.f, 0.f), bv = xv;
        if (xrow) xv = *(const float2*)(xrow + lk);
        if (brow) bv = *(const float2*)(brow + lk);
        for (int k0 = 0; k0 < 500; k0 += 8) {
            __syncthreads();
            Xs[(lk + 0) * 132 + lr] = xv.x; Xs[(lk + 1) * 132 + lr] = xv.y;
            if (lr < BC) {
                Bs[(lk + 0) * 132 + lr] = bv.x; Bs[(lk + 1) * 132 + lr] = bv.y;
            }
            __syncthreads();
            if (k0 + 8 < 500) {
                int kn = k0 + 8 + lk;
                xv = make_float2(0.f, 0.f); bv = xv;
                if (kn + 1 < 500) {
                    if (xrow) xv = *(const float2*)(xrow + kn);
                    if (brow) bv = *(const float2*)(brow + kn);
                } else if (kn < 500) {
                    if (xrow) xv.x = xrow[kn];
                    if (brow) bv.x = brow[kn];
                }
            }
#pragma unroll
            for (int kk = 0; kk < 8; kk++) {
                float4 a = *(const float4*)&Xs[kk * 132 + rr];
                ull av0 = splat2(a.x), av1 = splat2(a.y), av2 = splat2(a.z), av3 = splat2(a.w);
                ulonglong2 q0 = ((const ulonglong2*)&Bs[kk * 132 + tc])[0];
                ffma2(acc[0][0], av0, q0.x); ffma2(acc[0][1], av0, q0.y);
                ffma2(acc[1][0], av1, q0.x); ffma2(acc[1][1], av1, q0.y);
                ffma2(acc[2][0], av2, q0.x); ffma2(acc[2][1], av2, q0.y);
                ffma2(acc[3][0], av3, q0.x); ffma2(acc[3][1], av3, q0.y);
                if (UPT == 4) {
                    ulonglong2 q1 = ((const ulonglong2*)&Bs[kk * 132 + tc])[1];
                    ffma2(acc[0][2], av0, q1.x); ffma2(acc[0][3], av0, q1.y);
                    ffma2(acc[1][2], av1, q1.x); ffma2(acc[1][3], av1, q1.y);
                    ffma2(acc[2][2], av2, q1.x); ffma2(acc[2][3], av2, q1.y);
                    ffma2(acc[3][2], av3, q1.x); ffma2(acc[3][3], av3, q1.y);
                }
            }
        }
#pragma unroll
        for (int i = 0; i < 4; i++) {
            int r = m0 + rr + i;
            if (r >= M) continue;
            int c = r >> 4, b = r & 15;
#pragma unroll
            for (int j = 0; j < UPT; j++) {
                float2 v = unpk(acc[i][j]);
                int col = n0 + tc + 2 * j;
                if (col < NC) {
                    int s = col / 500, w = col - s * 500;
                    Out[(s * CCH + c) * BN + b * 500 + w] = v.x;
                }
                if (col + 1 < NC) {
                    int s2 = (col + 1) / 500, w2 = (col + 1) - s2 * 500;
                    Out[(s2 * CCH + c) * BN + b * 500 + w2] = v.y;
                }
            }
        }
    }
}

// ---------- A^2 (setup, 512 threads) ----------
__device__ __forceinline__ void sq_tiles(const float* __restrict__ Af,
                                         const float* __restrict__ Ab, float* sm) {
    float* As = sm;             // [16][68]
    float* Bq = sm + 16 * 68;
    const int tid = threadIdx.x;
    for (int tile = blockIdx.x; tile < 128; tile += NBLK) {
        const float* A = (tile < 64) ? Af : Ab;
        const int dst = (tile < 64) ? 250000 : 750000;
        const int tt = tile & 63;
        const int m0 = (tt >> 3) * 64, n0 = (tt & 7) * 64;
        const int rg = (tid >> 4) * 2, cg = (tid & 15) * 4;
        float acc[2][4] = {};
        for (int k0 = 0; k0 < 500; k0 += 16) {
            __syncthreads();
#pragma unroll
            for (int q = 0; q < 2; q++) {
                int e = tid + q * 512;
                int r = e >> 4, kk = e & 15;
                float v = 0.f;
                int gr = m0 + r, gk = k0 + kk;
                if (gr < 500 && gk < 500) v = A[gr * 500 + gk];
                As[kk * 68 + r] = v;
                int kb = e >> 6, j = e & 63;
                float w = 0.f;
                int gk2 = k0 + kb, gc = n0 + j;
                if (gk2 < 500 && gc < 500) w = A[gk2 * 500 + gc];
                Bq[kb * 68 + j] = w;
            }
            __syncthreads();
#pragma unroll
            for (int kk = 0; kk < 16; kk++) {
                float a0 = As[kk * 68 + rg], a1 = As[kk * 68 + rg + 1];
                float b0 = Bq[kk * 68 + cg], b1 = Bq[kk * 68 + cg + 1];
                float b2 = Bq[kk * 68 + cg + 2], b3 = Bq[kk * 68 + cg + 3];
                acc[0][0] += a0 * b0; acc[0][1] += a0 * b1;
                acc[0][2] += a0 * b2; acc[0][3] += a0 * b3;
                acc[1][0] += a1 * b0; acc[1][1] += a1 * b1;
                acc[1][2] += a1 * b2; acc[1][3] += a1 * b3;
            }
        }
#pragma unroll
        for (int i = 0; i < 2; i++) {
            int r = m0 + rg + i;
            if (r >= 500) continue;
#pragma unroll
            for (int j = 0; j < 4; j++) {
                int c = n0 + cg + j;
                if (c < 500) g_M4[dst + r * 500 + c] = acc[i][j];
            }
        }
    }
}

// ---------- the single persistent kernel ----------
__global__ void __launch_bounds__(NT, 1) gril_persist(
    const float* __restrict__ x, const float* __restrict__ Af, const float* __restrict__ Ab,
    const int* __restrict__ mask,
    const float* __restrict__ Wr, const float* __restrict__ br,
    const float* __restrict__ Wu, const float* __restrict__ bu,
    const float* __restrict__ Wc, const float* __restrict__ bc,
    const float* __restrict__ Wfs, const float* __restrict__ bfs,
    const float* __restrict__ Wli, const float* __restrict__ bli,
    const float* __restrict__ Wgc, const float* __restrict__ bgc,
    const float* __restrict__ Wlo, const float* __restrict__ blo,
    const float* __restrict__ Wro, const float* __restrict__ bro,
    const float* __restrict__ pa,
    float* __restrict__ imp, float* __restrict__ pred, float* __restrict__ reps) {
    __shared__ float sm[2176];
    __shared__ float sm_out[64 * 128];
    const int tid = threadIdx.x;
    const int gid0 = blockIdx.x * NT + tid;
    const int gstr = NBLK * NT;

    // ---- setup ----
    for (int i = gid0; i < TT * BN; i += gstr) {
        int t = i & 127, bn = i >> 7;
        g_xT[t * BN + bn] = x[i];
        g_mT[t * BN + bn] = (float)mask[i];
    }
    for (int i = gid0; i < 250000; i += gstr) {
        float vf = Af[i], vb = Ab[i];
        g_M4[i] = vf; g_M4[500000 + i] = vb;
        g_M2[i] = vf; g_M2[250000 + i] = vb;
    }
    for (int i = gid0; i < 64 * BN; i += gstr) g_h[i] = 0.f;
    for (int i = gid0; i < 64 * 330; i += gstr) {
        int o = i / 330, j = i - o * 330;
        g_Wru[o * 330 + j] = Wr[i];
        g_Wru[(64 + o) * 330 + j] = Wu[i];
    }
    for (int i = gid0; i < 64 * 128; i += gstr) {
        int o = i >> 7, j = i & 127;
        float s = 0.f;
        for (int q = 0; q < 64; q++) s += Wlo[o * 128 + q] * Wgc[q * 128 + j];
        g_Wp[o * 192 + j] = s;
    }
    for (int i = gid0; i < 64 * 64; i += gstr) {
        int o = i >> 6, j = i & 63;
        g_Wp[o * 192 + 128 + j] = Wlo[o * 128 + 64 + j];
    }
    for (int i = gid0; i < 64; i += gstr) {
        float s = blo[i];
        for (int q = 0; q < 64; q++) s += Wlo[i * 128 + q] * bgc[q];
        g_bp[i] = s;
        g_bru[i] = br[i];
        g_bru[64 + i] = bu[i];
    }
    sq_tiles(Af, Ab, sm);
    gsync();

    // stage A at t=0 (h == 0)
    for (int bn = gid0; bn < BN; bn += gstr) {
        float acc = __ldg(bfs);
        pred[bn * TT] = acc;
        float m = g_mT[bn];
        g_x1[bn] = (m > 0.5f) ? g_xT[bn] : acc;
    }
    gsync();

    // ---- time loop ----
    for (int t = 0; t < TT; t++) {
        conv_stage<0, 0>(t, Wli, bli, sm, sm_out, 0, 0, 0, 0, 0, imp, pred, reps);
        gsync();
        diff_stage<0>(t, sm);
        gsync();
        conv_stage<1, 1>(t, g_Wp, g_bp, sm, sm_out, Wro, bro, 0, 0, pa, imp, pred, reps);
        gsync();
        diff_stage<1>(t, sm);
        gsync();
        conv_stage<2, 2>(t, g_Wru, g_bru, sm, sm_out, 0, 0, 0, 0, 0, imp, pred, reps);
        gsync();
        diff_stage<2>(t, sm);
        gsync();
        conv_stage<3, 3>(t, Wc, bc, sm, sm_out, 0, 0, Wfs, bfs, 0, imp, pred, reps);
        gsync();
    }
}

// ---------- host: ONE kernel node ----------
extern "C" void kernel_launch(void* const* d_in, const int* in_sizes, int n_in,
                              void* d_out, int out_size) {
    const float* x    = (const float*)d_in[0];
    const float* Af   = (const float*)d_in[1];
    const float* Ab   = (const float*)d_in[2];
    const int*   mask = (const int*)  d_in[3];
    const float* Wr   = (const float*)d_in[4];
    const float* br   = (const float*)d_in[5];
    const float* Wu   = (const float*)d_in[6];
    const float* bu   = (const float*)d_in[7];
    const float* Wc   = (const float*)d_in[8];
    const float* bc   = (const float*)d_in[9];
    const float* Wfs  = (const float*)d_in[10];
    const float* bfs  = (const float*)d_in[11];
    const float* Wli  = (const float*)d_in[12];
    const float* bli  = (const float*)d_in[13];
    const float* Wgc  = (const float*)d_in[14];
    const float* bgc  = (const float*)d_in[15];
    const float* Wlo  = (const float*)d_in[16];
    const float* blo  = (const float*)d_in[17];
    const float* Wro  = (const float*)d_in[18];
    const float* bro  = (const float*)d_in[19];
    const float* pa   = (const float*)d_in[20];

    float* imp  = (float*)d_out;
    float* pred = imp + 16 * 500 * 128;
    float* reps = imp + 2 * 16 * 500 * 128;

    gril_persist<<<NBLK, NT>>>(x, Af, Ab, mask, Wr, br, Wu, bu, Wc, bc,
                               Wfs, bfs, Wli, bli, Wgc, bgc, Wlo, blo,
                               Wro, bro, pa, imp, pred, reps);
}